// round 16
// baseline (speedup 1.0000x reference)
#include <cuda_runtime.h>
#include <cuda_bf16.h>
#include <mma.h>
#include <cstdint>

using namespace nvcuda;

#define B_  256
#define H_  1024
#define L_  128
#define V_  32000

// ---------------- scratch (device globals) ----------------
__device__ float g_xcat[B_ * 2 * H_];
__device__ float g_x   [B_ * H_];
__device__ float g_gx  [B_ * 3 * H_];
__device__ float g_gh  [B_ * 3 * H_];
__device__ __nv_bfloat16 g_hb[B_ * H_];          // bf16 h_new
__device__ __nv_bfloat16 g_wb[(size_t)V_ * H_];  // bf16 out_w (fits L2: 64MB)

// output layout: [logp (256x32000) | h_new (256x1024) | attn_weights (256x128)]
#define OFF_H    (B_ * V_)
#define OFF_ATTN (OFF_H + B_ * H_)

// fp32x4 -> packed bf16x2 pair via PTX cvt
__device__ __forceinline__ uint2 cvt_f4_bf16(float4 v) {
    uint2 u;
    asm("cvt.rn.bf16x2.f32 %0, %1, %2;" : "=r"(u.x) : "f"(v.y), "f"(v.x));
    asm("cvt.rn.bf16x2.f32 %0, %1, %2;" : "=r"(u.y) : "f"(v.w), "f"(v.z));
    return u;
}

// ====================================================================
// K0: W fp32 -> bf16 (side stream; hidden under main chain)
// ====================================================================
__global__ __launch_bounds__(256)
void convert_w_kernel(const float* __restrict__ W, __nv_bfloat16* __restrict__ Wb) {
    const size_t i = ((size_t)blockIdx.x * 256 + threadIdx.x) * 8;
    const float4 v0 = *(const float4*)&W[i];
    const float4 v1 = *(const float4*)&W[i + 4];
    const uint2 a = cvt_f4_bf16(v0), b = cvt_f4_bf16(v1);
    *(uint4*)&Wb[i] = make_uint4(a.x, a.y, b.x, b.y);
}

// ====================================================================
// K1: attention (gather + logits + softmax + einsum, LDG.128 einsum)
// ====================================================================
__global__ void attn_kernel(const int* __restrict__ ids,
                            const float* __restrict__ hidden,
                            const float* __restrict__ enc,
                            const float* __restrict__ emb,
                            const float* __restrict__ attn_w,
                            const float* __restrict__ attn_b,
                            float* __restrict__ attn_out,
                            float* __restrict__ xcat) {
    __shared__ float sx[2 * H_];
    __shared__ float sw[L_];
    __shared__ float sred[256];

    const int b = blockIdx.x;
    const int tid = threadIdx.x;
    const int id = ids[b];

    for (int i = tid; i < H_; i += 256) {
        sx[i]      = emb[id * H_ + i];
        sx[H_ + i] = hidden[b * H_ + i];
    }
    __syncthreads();

    const int warp = tid >> 5, lane = tid & 31;
    for (int l = warp; l < L_; l += 8) {
        const float* wr = attn_w + l * (2 * H_);
        float s = 0.f;
        #pragma unroll 8
        for (int k = lane; k < 2 * H_; k += 32) s += sx[k] * wr[k];
        #pragma unroll
        for (int o = 16; o; o >>= 1) s += __shfl_down_sync(0xffffffffu, s, o);
        if (lane == 0) sw[l] = s + attn_b[l];
    }
    __syncthreads();

    sred[tid] = (tid < L_) ? sw[tid] : -1e30f;
    __syncthreads();
    #pragma unroll
    for (int s2 = 128; s2 >= 1; s2 >>= 1) {
        if (tid < s2) sred[tid] = fmaxf(sred[tid], sred[tid + s2]);
        __syncthreads();
    }
    const float m = sred[0];
    __syncthreads();
    float e = 0.f;
    if (tid < L_) e = expf(sw[tid] - m);
    sred[tid] = e;
    __syncthreads();
    #pragma unroll
    for (int s2 = 128; s2 >= 1; s2 >>= 1) {
        if (tid < s2) sred[tid] += sred[tid + s2];
        __syncthreads();
    }
    const float inv = 1.0f / sred[0];
    __syncthreads();
    if (tid < L_) {
        const float w = e * inv;
        sw[tid] = w;
        attn_out[b * L_ + tid] = w;
    }
    __syncthreads();

    const float* eb = enc + (size_t)b * L_ * H_;
    const int col = tid * 4;
    float a0 = 0.f, a1 = 0.f, a2 = 0.f, a3 = 0.f;
    #pragma unroll 4
    for (int l = 0; l < L_; ++l) {
        const float w = sw[l];
        const float4 v = *(const float4*)(eb + (size_t)l * H_ + col);
        a0 = fmaf(w, v.x, a0);
        a1 = fmaf(w, v.y, a1);
        a2 = fmaf(w, v.z, a2);
        a3 = fmaf(w, v.w, a3);
    }
    float* xc = xcat + b * 2 * H_;
    *(float4*)(xc + col)      = *(const float4*)(sx + col);
    *(float4*)(xc + H_ + col) = make_float4(a0, a1, a2, a3);
}

// ====================================================================
// init: gh = b_hh, gx = b_ih, x = comb_b
// ====================================================================
__global__ void init_bias_kernel(float* __restrict__ gh, const float* __restrict__ b_hh,
                                 float* __restrict__ gx, const float* __restrict__ b_ih,
                                 float* __restrict__ x,  const float* __restrict__ comb_b) {
    const int i = blockIdx.x * 256 + threadIdx.x;
    const int n3 = i % (3 * H_);
    gh[i] = b_hh[n3];
    gx[i] = b_ih[n3];
    if (i < B_ * H_) x[i] = comb_b[i & (H_ - 1)];
}

// ====================================================================
// split-K tf32 GEMM: C += A[M,k0:k0+kspan] @ W[N, k0:]^T  (atomicAdd)
// ====================================================================
#define TLD 40
#define TLDC 72

__global__ __launch_bounds__(128)
void gemm_tf32_splitk(const float* __restrict__ A,
                      const float* __restrict__ W,
                      float* __restrict__ C,
                      int K, int kspan, int N, int relu_a) {
    __shared__ __align__(16) float As[2][64 * TLD];
    __shared__ __align__(16) float Bs[2][64 * TLD];

    const int n0 = blockIdx.x * 64;
    const int m0 = blockIdx.y * 64;
    const int k0 = blockIdx.z * kspan;
    const int tid = threadIdx.x;
    const int warp = tid >> 5;
    const int wm = warp >> 1, wn = warp & 1;
    const int lr = tid >> 3;
    const int lc = (tid & 7) * 4;

    wmma::fragment<wmma::accumulator, 16, 16, 8, float> c[2][2];
    #pragma unroll
    for (int i = 0; i < 2; i++)
        #pragma unroll
        for (int j = 0; j < 2; j++) wmma::fill_fragment(c[i][j], 0.0f);

    float4 ra[4], rb[4];
    #pragma unroll
    for (int i = 0; i < 4; i++) {
        ra[i] = *(const float4*)&A[(size_t)(m0 + lr + i * 16) * K + k0 + lc];
        rb[i] = *(const float4*)&W[(size_t)(n0 + lr + i * 16) * K + k0 + lc];
    }
    if (relu_a) {
        #pragma unroll
        for (int i = 0; i < 4; i++) {
            ra[i].x = fmaxf(ra[i].x, 0.f); ra[i].y = fmaxf(ra[i].y, 0.f);
            ra[i].z = fmaxf(ra[i].z, 0.f); ra[i].w = fmaxf(ra[i].w, 0.f);
        }
    }

    const int NT = kspan >> 5;
    for (int kt = 0; kt < NT; kt++) {
        const int cur = kt & 1;
        #pragma unroll
        for (int i = 0; i < 4; i++) {
            *(float4*)&As[cur][(lr + i * 16) * TLD + lc] = ra[i];
            *(float4*)&Bs[cur][(lr + i * 16) * TLD + lc] = rb[i];
        }
        __syncthreads();
        if (kt + 1 < NT) {
            const int ko = k0 + (kt + 1) * 32 + lc;
            #pragma unroll
            for (int i = 0; i < 4; i++) {
                ra[i] = *(const float4*)&A[(size_t)(m0 + lr + i * 16) * K + ko];
                rb[i] = *(const float4*)&W[(size_t)(n0 + lr + i * 16) * K + ko];
            }
            if (relu_a) {
                #pragma unroll
                for (int i = 0; i < 4; i++) {
                    ra[i].x = fmaxf(ra[i].x, 0.f); ra[i].y = fmaxf(ra[i].y, 0.f);
                    ra[i].z = fmaxf(ra[i].z, 0.f); ra[i].w = fmaxf(ra[i].w, 0.f);
                }
            }
        }
        #pragma unroll
        for (int kk = 0; kk < 4; kk++) {
            wmma::fragment<wmma::matrix_a, 16, 16, 8, wmma::precision::tf32, wmma::row_major> a[2];
            wmma::fragment<wmma::matrix_b, 16, 16, 8, wmma::precision::tf32, wmma::col_major> bf[2];
            #pragma unroll
            for (int i = 0; i < 2; i++) {
                wmma::load_matrix_sync(a[i], &As[cur][(wm * 32 + i * 16) * TLD + kk * 8], TLD);
                #pragma unroll
                for (int t = 0; t < a[i].num_elements; t++)
                    a[i].x[t] = wmma::__float_to_tf32(a[i].x[t]);
            }
            #pragma unroll
            for (int j = 0; j < 2; j++) {
                wmma::load_matrix_sync(bf[j], &Bs[cur][(wn * 32 + j * 16) * TLD + kk * 8], TLD);
                #pragma unroll
                for (int t = 0; t < bf[j].num_elements; t++)
                    bf[j].x[t] = wmma::__float_to_tf32(bf[j].x[t]);
            }
            #pragma unroll
            for (int i = 0; i < 2; i++)
                #pragma unroll
                for (int j = 0; j < 2; j++)
                    wmma::mma_sync(c[i][j], a[i], bf[j], c[i][j]);
        }
    }

    __syncthreads();
    float* Cs = (float*)As;
    #pragma unroll
    for (int i = 0; i < 2; i++)
        #pragma unroll
        for (int j = 0; j < 2; j++)
            wmma::store_matrix_sync(&Cs[(wm * 32 + i * 16) * TLDC + wn * 32 + j * 16],
                                    c[i][j], TLDC, wmma::mem_row_major);
    __syncthreads();
    for (int i = tid; i < 64 * 64; i += 128) {
        const int mm = i >> 6, nn = i & 63;
        atomicAdd(&C[(size_t)(m0 + mm) * N + n0 + nn], Cs[mm * TLDC + nn]);
    }
}

// ====================================================================
// K4: GRU gates (fp32 h_new output + bf16 copy for vocab)
// ====================================================================
__global__ void gru_gate_kernel(const float* __restrict__ gx,
                                const float* __restrict__ gh,
                                const float* __restrict__ hidden,
                                float* __restrict__ hout,
                                __nv_bfloat16* __restrict__ hb) {
    const int idx = blockIdx.x * blockDim.x + threadIdx.x;
    const int b = idx >> 10, j = idx & (H_ - 1);
    const float* gxb = gx + b * 3 * H_;
    const float* ghb = gh + b * 3 * H_;
    const float xr = gxb[j],          hr = ghb[j];
    const float xz = gxb[H_ + j],     hz = ghb[H_ + j];
    const float xn = gxb[2 * H_ + j], hn = ghb[2 * H_ + j];
    const float r = 1.0f / (1.0f + expf(-(xr + hr)));
    const float z = 1.0f / (1.0f + expf(-(xz + hz)));
    const float n = tanhf(xn + r * hn);
    const float h = (1.0f - z) * n + z * hidden[idx];
    hout[idx] = h;
    hb[idx] = __float2bfloat16(h);
}

// ====================================================================
// K5: bf16 vocab GEMM  logits = hb[B,H] @ wb[V,H]^T  (all-bf16 inputs)
// BM=128, BN=128, BK=32, 256 threads (8 warps 2x4, warp tile 64x32),
// grid (2, 250): m-half pairs adjacent; bf16 W (64MB) is L2-resident so
// the second m-half reads W from L2, not DRAM. 2 CTAs/SM.
// Per thread per k-iter: 4x LDG.128 + 4x STS.128. Single sync.
// ====================================================================
#define VLD 40                        // bf16 leading dim (80B rows)
#define VAS (128 * VLD)
#define VBS (128 * VLD)
#define VOC_SMEM ((2 * VAS + 2 * VBS) * 2)   // 40960 bytes

__global__ __launch_bounds__(256, 2)
void gemm_bf16_vocab(const __nv_bfloat16* __restrict__ A,
                     const __nv_bfloat16* __restrict__ W,
                     float* __restrict__ C) {
    extern __shared__ __align__(16) __nv_bfloat16 sm[];
    __nv_bfloat16* As = sm;            // [2][VAS]
    __nv_bfloat16* Bs = sm + 2 * VAS;  // [2][VBS]

    const int m0 = blockIdx.x * 128;   // 0 / 128 (fast dim -> pair co-resident)
    const int n0 = blockIdx.y * 128;
    const int tid = threadIdx.x;
    const int warp = tid >> 5;
    const int wm = warp >> 2;          // 0..1 (64 rows)
    const int wn = warp & 3;           // 0..3 (32 cols)
    const int row = tid >> 1;          // 0..127
    const int hc  = (tid & 1) * 16;    // 0 / 16 (bf16 elems)

    wmma::fragment<wmma::accumulator, 16, 16, 16, float> c[4][2];
    #pragma unroll
    for (int i = 0; i < 4; i++)
        #pragma unroll
        for (int j = 0; j < 2; j++) wmma::fill_fragment(c[i][j], 0.0f);

    // register prefetch: 16 bf16 A (2x uint4) + 16 bf16 W (2x uint4)
    uint4 ra0, ra1, rw0, rw1;
    {
        const uint4* pA = (const uint4*)&A[(size_t)(m0 + row) * H_ + hc];
        ra0 = pA[0]; ra1 = pA[1];
        const uint4* pW = (const uint4*)&W[(size_t)(n0 + row) * H_ + hc];
        rw0 = pW[0]; rw1 = pW[1];
    }

    const int NT = H_ / 32;   // 32
    for (int kt = 0; kt < NT; kt++) {
        const int cur = kt & 1;
        {
            uint4* sa = (uint4*)&As[cur * VAS + row * VLD + hc];
            sa[0] = ra0; sa[1] = ra1;
            uint4* sb = (uint4*)&Bs[cur * VBS + row * VLD + hc];
            sb[0] = rw0; sb[1] = rw1;
        }
        __syncthreads();
        if (kt + 1 < NT) {
            const int ko = (kt + 1) * 32 + hc;
            const uint4* pA = (const uint4*)&A[(size_t)(m0 + row) * H_ + ko];
            ra0 = pA[0]; ra1 = pA[1];
            const uint4* pW = (const uint4*)&W[(size_t)(n0 + row) * H_ + ko];
            rw0 = pW[0]; rw1 = pW[1];
        }
        const __nv_bfloat16* Ac = As + cur * VAS;
        const __nv_bfloat16* Bc = Bs + cur * VBS;
        #pragma unroll
        for (int kk = 0; kk < 2; kk++) {
            wmma::fragment<wmma::matrix_a, 16, 16, 16, __nv_bfloat16, wmma::row_major> a[4];
            wmma::fragment<wmma::matrix_b, 16, 16, 16, __nv_bfloat16, wmma::col_major> bf[2];
            #pragma unroll
            for (int i = 0; i < 4; i++)
                wmma::load_matrix_sync(a[i], &Ac[(wm * 64 + i * 16) * VLD + kk * 16], VLD);
            #pragma unroll
            for (int j = 0; j < 2; j++)
                wmma::load_matrix_sync(bf[j], &Bc[(wn * 32 + j * 16) * VLD + kk * 16], VLD);
            #pragma unroll
            for (int i = 0; i < 4; i++)
                #pragma unroll
                for (int j = 0; j < 2; j++)
                    wmma::mma_sync(c[i][j], a[i], bf[j], c[i][j]);
        }
    }

    #pragma unroll
    for (int i = 0; i < 4; i++)
        #pragma unroll
        for (int j = 0; j < 2; j++)
            wmma::store_matrix_sync(&C[(size_t)(m0 + wm * 64 + i * 16) * V_ + n0 + wn * 32 + j * 16],
                                    c[i][j], V_, wmma::mem_row_major);
}

// ====================================================================
// K6: bias + log_softmax (row in registers)
// ====================================================================
__global__ __launch_bounds__(1024)
void logsoftmax_kernel(float* __restrict__ logits,
                       const float* __restrict__ ob) {
    __shared__ float sred[32];
    const int b = blockIdx.x;
    const int tid = threadIdx.x;
    const int lane = tid & 31, wid = tid >> 5;
    float* row = logits + (size_t)b * V_;

    float v[32];
    float m = -1e30f;
    #pragma unroll
    for (int k = 0; k < 32; k++) {
        const int idx = k * 1024 + tid;
        float t = -1e30f;
        if (idx < V_) t = row[idx] + ob[idx];
        v[k] = t;
        m = fmaxf(m, t);
    }
    #pragma unroll
    for (int o = 16; o; o >>= 1) m = fmaxf(m, __shfl_xor_sync(0xffffffffu, m, o));
    if (lane == 0) sred[wid] = m;
    __syncthreads();
    if (wid == 0) {
        float t = sred[lane];
        #pragma unroll
        for (int o = 16; o; o >>= 1) t = fmaxf(t, __shfl_xor_sync(0xffffffffu, t, o));
        if (lane == 0) sred[0] = t;
    }
    __syncthreads();
    m = sred[0];
    __syncthreads();

    float s = 0.f;
    #pragma unroll
    for (int k = 0; k < 32; k++) {
        const int idx = k * 1024 + tid;
        if (idx < V_) {
            v[k] = v[k] - m;
            s += expf(v[k]);
        }
    }
    #pragma unroll
    for (int o = 16; o; o >>= 1) s += __shfl_xor_sync(0xffffffffu, s, o);
    if (lane == 0) sred[wid] = s;
    __syncthreads();
    if (wid == 0) {
        float t = sred[lane];
        #pragma unroll
        for (int o = 16; o; o >>= 1) t += __shfl_xor_sync(0xffffffffu, t, o);
        if (lane == 0) sred[0] = t;
    }
    __syncthreads();
    const float lse = logf(sred[0]);

    #pragma unroll
    for (int k = 0; k < 32; k++) {
        const int idx = k * 1024 + tid;
        if (idx < V_) row[idx] = v[k] - lse;
    }
}

// ====================================================================
extern "C" void kernel_launch(void* const* d_in, const int* in_sizes, int n_in,
                              void* d_out, int out_size) {
    const int*   ids    = (const int*)  d_in[0];
    const float* hidden = (const float*)d_in[1];
    const float* enc    = (const float*)d_in[2];
    const float* emb    = (const float*)d_in[3];
    const float* attn_w = (const float*)d_in[4];
    const float* attn_b = (const float*)d_in[5];
    const float* comb_w = (const float*)d_in[6];
    const float* comb_b = (const float*)d_in[7];
    const float* w_ih   = (const float*)d_in[8];
    const float* b_ih   = (const float*)d_in[9];
    const float* w_hh   = (const float*)d_in[10];
    const float* b_hh   = (const float*)d_in[11];
    const float* out_w  = (const float*)d_in[12];
    const float* out_b  = (const float*)d_in[13];

    float* out      = (float*)d_out;
    float* out_logp = out;
    float* out_h    = out + OFF_H;
    float* out_attn = out + OFF_ATTN;

    float *xcat, *x, *gx, *gh;
    __nv_bfloat16 *hb, *wb;
    cudaGetSymbolAddress((void**)&xcat, g_xcat);
    cudaGetSymbolAddress((void**)&x,    g_x);
    cudaGetSymbolAddress((void**)&gx,   g_gx);
    cudaGetSymbolAddress((void**)&gh,   g_gh);
    cudaGetSymbolAddress((void**)&hb,   g_hb);
    cudaGetSymbolAddress((void**)&wb,   g_wb);

    cudaFuncSetAttribute(gemm_bf16_vocab,
                         cudaFuncAttributeMaxDynamicSharedMemorySize, VOC_SMEM);

    static cudaStream_t s_side = nullptr;
    static cudaEvent_t ev_fork = nullptr, ev_init = nullptr, ev_side = nullptr;
    if (!s_side) {
        cudaStreamCreateWithFlags(&s_side, cudaStreamNonBlocking);
        cudaEventCreateWithFlags(&ev_fork, cudaEventDisableTiming);
        cudaEventCreateWithFlags(&ev_init, cudaEventDisableTiming);
        cudaEventCreateWithFlags(&ev_side, cudaEventDisableTiming);
    }

    // fork side stream at the very start
    cudaEventRecord(ev_fork, 0);
    cudaStreamWaitEvent(s_side, ev_fork, 0);
    // side: convert W -> bf16 (depends only on inputs)
    convert_w_kernel<<<(V_ * (H_ / 8)) / 256, 256, 0, s_side>>>(out_w, wb);

    // main: init biases
    init_bias_kernel<<<B_ * 3 * H_ / 256, 256>>>(gh, b_hh, gx, b_ih, x, comb_b);
    cudaEventRecord(ev_init, 0);

    // side: gh += hidden @ w_hh^T (needs init'd gh)
    cudaStreamWaitEvent(s_side, ev_init, 0);
    gemm_tf32_splitk<<<dim3(48, 4, 8), 128, 0, s_side>>>(hidden, w_hh, gh, H_, 128, 3 * H_, 0);
    cudaEventRecord(ev_side, s_side);

    // main chain: attn -> comb -> gx (concurrent with side branch)
    attn_kernel<<<B_, 256>>>(ids, hidden, enc, emb, attn_w, attn_b, out_attn, xcat);
    gemm_tf32_splitk<<<dim3(16, 4, 16), 128>>>(xcat, comb_w, x, 2 * H_, 128, H_, 0);
    gemm_tf32_splitk<<<dim3(48, 4, 8), 128>>>(x, w_ih, gx, H_, 128, 3 * H_, 1);

    // join: gru needs gx (main) + gh (side); vocab needs wb (side, earlier)
    cudaStreamWaitEvent(0, ev_side, 0);
    gru_gate_kernel<<<B_ * H_ / 256, 256>>>(gx, gh, hidden, out_h, hb);

    gemm_bf16_vocab<<<dim3(2, V_ / 128), 256, VOC_SMEM>>>(hb, wb, out_logp);
    logsoftmax_kernel<<<B_, 1024>>>(out_logp, out_b);
}

// round 17
// speedup vs baseline: 1.3112x; 1.3112x over previous
#include <cuda_runtime.h>
#include <cuda_bf16.h>
#include <mma.h>
#include <cstdint>

using namespace nvcuda;

#define B_  256
#define H_  1024
#define L_  128
#define V_  32000

// ---------------- scratch (device globals) ----------------
__device__ float g_xcat[B_ * 2 * H_];
__device__ float g_x   [B_ * H_];
__device__ float g_gx  [B_ * 3 * H_];
__device__ float g_gh  [B_ * 3 * H_];

// output layout: [logp (256x32000) | h_new (256x1024) | attn_weights (256x128)]
#define OFF_H    (B_ * V_)
#define OFF_ATTN (OFF_H + B_ * H_)

// fp32x4 -> packed bf16x2 pair via PTX cvt
__device__ __forceinline__ uint2 cvt_f4_bf16(float4 v) {
    uint2 u;
    asm("cvt.rn.bf16x2.f32 %0, %1, %2;" : "=r"(u.x) : "f"(v.y), "f"(v.x));
    asm("cvt.rn.bf16x2.f32 %0, %1, %2;" : "=r"(u.y) : "f"(v.w), "f"(v.z));
    return u;
}

// ====================================================================
// K1: attention — 512 threads, einsum l-split 2-way
// ====================================================================
__global__ __launch_bounds__(512)
void attn_kernel(const int* __restrict__ ids,
                 const float* __restrict__ hidden,
                 const float* __restrict__ enc,
                 const float* __restrict__ emb,
                 const float* __restrict__ attn_w,
                 const float* __restrict__ attn_b,
                 float* __restrict__ attn_out,
                 float* __restrict__ xcat) {
    __shared__ float sx[2 * H_];
    __shared__ float sw[L_];
    __shared__ float sred[128];
    __shared__ float spart[H_];      // partial einsum from half 1

    const int b = blockIdx.x;
    const int tid = threadIdx.x;
    const int id = ids[b];

    for (int i = tid; i < H_; i += 512) {
        sx[i]      = emb[id * H_ + i];
        sx[H_ + i] = hidden[b * H_ + i];
    }
    __syncthreads();

    const int warp = tid >> 5, lane = tid & 31;
    // logits: 16 warps, each handles 8 of 128 rows
    for (int l = warp; l < L_; l += 16) {
        const float* wr = attn_w + l * (2 * H_);
        float s = 0.f;
        #pragma unroll 8
        for (int k = lane; k < 2 * H_; k += 32) s += sx[k] * wr[k];
        #pragma unroll
        for (int o = 16; o; o >>= 1) s += __shfl_down_sync(0xffffffffu, s, o);
        if (lane == 0) sw[l] = s + attn_b[l];
    }
    __syncthreads();

    // softmax over L=128 (first 128 threads)
    if (tid < 128) sred[tid] = sw[tid];
    __syncthreads();
    #pragma unroll
    for (int s2 = 64; s2 >= 1; s2 >>= 1) {
        if (tid < s2) sred[tid] = fmaxf(sred[tid], sred[tid + s2]);
        __syncthreads();
    }
    const float m = sred[0];
    __syncthreads();
    float e = 0.f;
    if (tid < L_) e = expf(sw[tid] - m);
    if (tid < 128) sred[tid] = e;
    __syncthreads();
    #pragma unroll
    for (int s2 = 64; s2 >= 1; s2 >>= 1) {
        if (tid < s2) sred[tid] += sred[tid + s2];
        __syncthreads();
    }
    const float inv = 1.0f / sred[0];
    __syncthreads();
    if (tid < L_) {
        const float w = e * inv;
        sw[tid] = w;
        attn_out[b * L_ + tid] = w;
    }
    __syncthreads();

    // einsum: 2-way l-split. cg = col group (256 groups of 4 cols),
    // half in {0,1} covers l in [half*64, half*64+64).
    const int cg   = tid & 255;
    const int half = tid >> 8;
    const int col  = cg * 4;
    const float* eb = enc + (size_t)b * L_ * H_ + (size_t)(half * 64) * H_;
    float a0 = 0.f, a1 = 0.f, a2 = 0.f, a3 = 0.f;
    #pragma unroll 8
    for (int l = 0; l < 64; ++l) {
        const float w = sw[half * 64 + l];
        const float4 v = *(const float4*)(eb + (size_t)l * H_ + col);
        a0 = fmaf(w, v.x, a0);
        a1 = fmaf(w, v.y, a1);
        a2 = fmaf(w, v.z, a2);
        a3 = fmaf(w, v.w, a3);
    }
    if (half == 1) {
        *(float4*)(spart + col) = make_float4(a0, a1, a2, a3);
    }
    __syncthreads();
    if (half == 0) {
        const float4 p = *(const float4*)(spart + col);
        float* xc = xcat + b * 2 * H_;
        *(float4*)(xc + col)      = *(const float4*)(sx + col);
        *(float4*)(xc + H_ + col) = make_float4(a0 + p.x, a1 + p.y, a2 + p.z, a3 + p.w);
    }
}

// ====================================================================
// init: gh = b_hh, gx = b_ih, x = comb_b
// ====================================================================
__global__ void init_bias_kernel(float* __restrict__ gh, const float* __restrict__ b_hh,
                                 float* __restrict__ gx, const float* __restrict__ b_ih,
                                 float* __restrict__ x,  const float* __restrict__ comb_b) {
    const int i = blockIdx.x * 256 + threadIdx.x;
    const int n3 = i % (3 * H_);
    gh[i] = b_hh[n3];
    gx[i] = b_ih[n3];
    if (i < B_ * H_) x[i] = comb_b[i & (H_ - 1)];
}

// ====================================================================
// split-K tf32 GEMM: C += A[M,k0:k0+kspan] @ W[N, k0:]^T  (atomicAdd)
// ====================================================================
#define TLD 40
#define TLDC 72

__global__ __launch_bounds__(128)
void gemm_tf32_splitk(const float* __restrict__ A,
                      const float* __restrict__ W,
                      float* __restrict__ C,
                      int K, int kspan, int N, int relu_a) {
    __shared__ __align__(16) float As[2][64 * TLD];
    __shared__ __align__(16) float Bs[2][64 * TLD];

    const int n0 = blockIdx.x * 64;
    const int m0 = blockIdx.y * 64;
    const int k0 = blockIdx.z * kspan;
    const int tid = threadIdx.x;
    const int warp = tid >> 5;
    const int wm = warp >> 1, wn = warp & 1;
    const int lr = tid >> 3;
    const int lc = (tid & 7) * 4;

    wmma::fragment<wmma::accumulator, 16, 16, 8, float> c[2][2];
    #pragma unroll
    for (int i = 0; i < 2; i++)
        #pragma unroll
        for (int j = 0; j < 2; j++) wmma::fill_fragment(c[i][j], 0.0f);

    float4 ra[4], rb[4];
    #pragma unroll
    for (int i = 0; i < 4; i++) {
        ra[i] = *(const float4*)&A[(size_t)(m0 + lr + i * 16) * K + k0 + lc];
        rb[i] = *(const float4*)&W[(size_t)(n0 + lr + i * 16) * K + k0 + lc];
    }
    if (relu_a) {
        #pragma unroll
        for (int i = 0; i < 4; i++) {
            ra[i].x = fmaxf(ra[i].x, 0.f); ra[i].y = fmaxf(ra[i].y, 0.f);
            ra[i].z = fmaxf(ra[i].z, 0.f); ra[i].w = fmaxf(ra[i].w, 0.f);
        }
    }

    const int NT = kspan >> 5;
    for (int kt = 0; kt < NT; kt++) {
        const int cur = kt & 1;
        #pragma unroll
        for (int i = 0; i < 4; i++) {
            *(float4*)&As[cur][(lr + i * 16) * TLD + lc] = ra[i];
            *(float4*)&Bs[cur][(lr + i * 16) * TLD + lc] = rb[i];
        }
        __syncthreads();
        if (kt + 1 < NT) {
            const int ko = k0 + (kt + 1) * 32 + lc;
            #pragma unroll
            for (int i = 0; i < 4; i++) {
                ra[i] = *(const float4*)&A[(size_t)(m0 + lr + i * 16) * K + ko];
                rb[i] = *(const float4*)&W[(size_t)(n0 + lr + i * 16) * K + ko];
            }
            if (relu_a) {
                #pragma unroll
                for (int i = 0; i < 4; i++) {
                    ra[i].x = fmaxf(ra[i].x, 0.f); ra[i].y = fmaxf(ra[i].y, 0.f);
                    ra[i].z = fmaxf(ra[i].z, 0.f); ra[i].w = fmaxf(ra[i].w, 0.f);
                }
            }
        }
        #pragma unroll
        for (int kk = 0; kk < 4; kk++) {
            wmma::fragment<wmma::matrix_a, 16, 16, 8, wmma::precision::tf32, wmma::row_major> a[2];
            wmma::fragment<wmma::matrix_b, 16, 16, 8, wmma::precision::tf32, wmma::col_major> bf[2];
            #pragma unroll
            for (int i = 0; i < 2; i++) {
                wmma::load_matrix_sync(a[i], &As[cur][(wm * 32 + i * 16) * TLD + kk * 8], TLD);
                #pragma unroll
                for (int t = 0; t < a[i].num_elements; t++)
                    a[i].x[t] = wmma::__float_to_tf32(a[i].x[t]);
            }
            #pragma unroll
            for (int j = 0; j < 2; j++) {
                wmma::load_matrix_sync(bf[j], &Bs[cur][(wn * 32 + j * 16) * TLD + kk * 8], TLD);
                #pragma unroll
                for (int t = 0; t < bf[j].num_elements; t++)
                    bf[j].x[t] = wmma::__float_to_tf32(bf[j].x[t]);
            }
            #pragma unroll
            for (int i = 0; i < 2; i++)
                #pragma unroll
                for (int j = 0; j < 2; j++)
                    wmma::mma_sync(c[i][j], a[i], bf[j], c[i][j]);
        }
    }

    __syncthreads();
    float* Cs = (float*)As;
    #pragma unroll
    for (int i = 0; i < 2; i++)
        #pragma unroll
        for (int j = 0; j < 2; j++)
            wmma::store_matrix_sync(&Cs[(wm * 32 + i * 16) * TLDC + wn * 32 + j * 16],
                                    c[i][j], TLDC, wmma::mem_row_major);
    __syncthreads();
    for (int i = tid; i < 64 * 64; i += 128) {
        const int mm = i >> 6, nn = i & 63;
        atomicAdd(&C[(size_t)(m0 + mm) * N + n0 + nn], Cs[mm * TLDC + nn]);
    }
}

// ====================================================================
// K4: GRU gates
// ====================================================================
__global__ void gru_gate_kernel(const float* __restrict__ gx,
                                const float* __restrict__ gh,
                                const float* __restrict__ hidden,
                                float* __restrict__ hout) {
    const int idx = blockIdx.x * blockDim.x + threadIdx.x;
    const int b = idx >> 10, j = idx & (H_ - 1);
    const float* gxb = gx + b * 3 * H_;
    const float* ghb = gh + b * 3 * H_;
    const float xr = gxb[j],          hr = ghb[j];
    const float xz = gxb[H_ + j],     hz = ghb[H_ + j];
    const float xn = gxb[2 * H_ + j], hn = ghb[2 * H_ + j];
    const float r = 1.0f / (1.0f + expf(-(xr + hr)));
    const float z = 1.0f / (1.0f + expf(-(xz + hz)));
    const float n = tanhf(xn + r * hn);
    hout[idx] = (1.0f - z) * n + z * hidden[idx];
}

// ====================================================================
// K5: bf16 vocab GEMM — exact 284.7us-validated configuration
// BM=256 (W streamed once), BN=128, BK=32, 512 threads, single sync
// ====================================================================
#define VLD 40
#define VAS_STAGE (256 * VLD)
#define VBS_STAGE (128 * VLD)
#define VOC_SMEM ((2 * VAS_STAGE + 2 * VBS_STAGE) * 2)   // 61440 bytes

__global__ __launch_bounds__(512)
void gemm_bf16_vocab(const float* __restrict__ A,
                     const float* __restrict__ W,
                     float* __restrict__ C) {
    extern __shared__ __align__(16) __nv_bfloat16 sm[];
    __nv_bfloat16* As = sm;
    __nv_bfloat16* Bs = sm + 2 * VAS_STAGE;

    const int n0 = blockIdx.x * 128;
    const int tid = threadIdx.x;
    const int warp = tid >> 5;
    const int wm = warp >> 2;
    const int wn = warp & 3;
    const int lr = tid >> 3;
    const int lc = (tid & 7) * 4;

    wmma::fragment<wmma::accumulator, 16, 16, 16, float> c[4][2];
    #pragma unroll
    for (int i = 0; i < 4; i++)
        #pragma unroll
        for (int j = 0; j < 2; j++) wmma::fill_fragment(c[i][j], 0.0f);

    float4 ra[4], rb[2];
    #pragma unroll
    for (int i = 0; i < 4; i++)
        ra[i] = *(const float4*)&A[(size_t)(lr + i * 64) * H_ + lc];
    #pragma unroll
    for (int i = 0; i < 2; i++)
        rb[i] = *(const float4*)&W[(size_t)(n0 + lr + i * 64) * H_ + lc];

    const int NT = H_ / 32;
    for (int kt = 0; kt < NT; kt++) {
        const int cur = kt & 1;
        #pragma unroll
        for (int i = 0; i < 4; i++)
            *(uint2*)&As[cur * VAS_STAGE + (lr + i * 64) * VLD + lc] = cvt_f4_bf16(ra[i]);
        #pragma unroll
        for (int i = 0; i < 2; i++)
            *(uint2*)&Bs[cur * VBS_STAGE + (lr + i * 64) * VLD + lc] = cvt_f4_bf16(rb[i]);
        __syncthreads();
        if (kt + 1 < NT) {
            const int ko = (kt + 1) * 32 + lc;
            #pragma unroll
            for (int i = 0; i < 4; i++)
                ra[i] = *(const float4*)&A[(size_t)(lr + i * 64) * H_ + ko];
            #pragma unroll
            for (int i = 0; i < 2; i++)
                rb[i] = *(const float4*)&W[(size_t)(n0 + lr + i * 64) * H_ + ko];
        }
        const __nv_bfloat16* Ac = As + cur * VAS_STAGE;
        const __nv_bfloat16* Bc = Bs + cur * VBS_STAGE;
        #pragma unroll
        for (int kk = 0; kk < 2; kk++) {
            wmma::fragment<wmma::matrix_a, 16, 16, 16, __nv_bfloat16, wmma::row_major> a[4];
            wmma::fragment<wmma::matrix_b, 16, 16, 16, __nv_bfloat16, wmma::col_major> bf[2];
            #pragma unroll
            for (int i = 0; i < 4; i++)
                wmma::load_matrix_sync(a[i], &Ac[(wm * 64 + i * 16) * VLD + kk * 16], VLD);
            #pragma unroll
            for (int j = 0; j < 2; j++)
                wmma::load_matrix_sync(bf[j], &Bc[(wn * 32 + j * 16) * VLD + kk * 16], VLD);
            #pragma unroll
            for (int i = 0; i < 4; i++)
                #pragma unroll
                for (int j = 0; j < 2; j++)
                    wmma::mma_sync(c[i][j], a[i], bf[j], c[i][j]);
        }
    }

    #pragma unroll
    for (int i = 0; i < 4; i++)
        #pragma unroll
        for (int j = 0; j < 2; j++)
            wmma::store_matrix_sync(&C[(size_t)(wm * 64 + i * 16) * V_ + n0 + wn * 32 + j * 16],
                                    c[i][j], V_, wmma::mem_row_major);
}

// ====================================================================
// K6: bias + log_softmax (row in registers)
// ====================================================================
__global__ __launch_bounds__(1024)
void logsoftmax_kernel(float* __restrict__ logits,
                       const float* __restrict__ ob) {
    __shared__ float sred[32];
    const int b = blockIdx.x;
    const int tid = threadIdx.x;
    const int lane = tid & 31, wid = tid >> 5;
    float* row = logits + (size_t)b * V_;

    float v[32];
    float m = -1e30f;
    #pragma unroll
    for (int k = 0; k < 32; k++) {
        const int idx = k * 1024 + tid;
        float t = -1e30f;
        if (idx < V_) t = row[idx] + ob[idx];
        v[k] = t;
        m = fmaxf(m, t);
    }
    #pragma unroll
    for (int o = 16; o; o >>= 1) m = fmaxf(m, __shfl_xor_sync(0xffffffffu, m, o));
    if (lane == 0) sred[wid] = m;
    __syncthreads();
    if (wid == 0) {
        float t = sred[lane];
        #pragma unroll
        for (int o = 16; o; o >>= 1) t = fmaxf(t, __shfl_xor_sync(0xffffffffu, t, o));
        if (lane == 0) sred[0] = t;
    }
    __syncthreads();
    m = sred[0];
    __syncthreads();

    float s = 0.f;
    #pragma unroll
    for (int k = 0; k < 32; k++) {
        const int idx = k * 1024 + tid;
        if (idx < V_) {
            v[k] = v[k] - m;
            s += expf(v[k]);
        }
    }
    #pragma unroll
    for (int o = 16; o; o >>= 1) s += __shfl_xor_sync(0xffffffffu, s, o);
    if (lane == 0) sred[wid] = s;
    __syncthreads();
    if (wid == 0) {
        float t = sred[lane];
        #pragma unroll
        for (int o = 16; o; o >>= 1) t += __shfl_xor_sync(0xffffffffu, t, o);
        if (lane == 0) sred[0] = t;
    }
    __syncthreads();
    const float lse = logf(sred[0]);

    #pragma unroll
    for (int k = 0; k < 32; k++) {
        const int idx = k * 1024 + tid;
        if (idx < V_) row[idx] = v[k] - lse;
    }
}

// ====================================================================
extern "C" void kernel_launch(void* const* d_in, const int* in_sizes, int n_in,
                              void* d_out, int out_size) {
    const int*   ids    = (const int*)  d_in[0];
    const float* hidden = (const float*)d_in[1];
    const float* enc    = (const float*)d_in[2];
    const float* emb    = (const float*)d_in[3];
    const float* attn_w = (const float*)d_in[4];
    const float* attn_b = (const float*)d_in[5];
    const float* comb_w = (const float*)d_in[6];
    const float* comb_b = (const float*)d_in[7];
    const float* w_ih   = (const float*)d_in[8];
    const float* b_ih   = (const float*)d_in[9];
    const float* w_hh   = (const float*)d_in[10];
    const float* b_hh   = (const float*)d_in[11];
    const float* out_w  = (const float*)d_in[12];
    const float* out_b  = (const float*)d_in[13];

    float* out      = (float*)d_out;
    float* out_logp = out;
    float* out_h    = out + OFF_H;
    float* out_attn = out + OFF_ATTN;

    float *xcat, *x, *gx, *gh;
    cudaGetSymbolAddress((void**)&xcat, g_xcat);
    cudaGetSymbolAddress((void**)&x,    g_x);
    cudaGetSymbolAddress((void**)&gx,   g_gx);
    cudaGetSymbolAddress((void**)&gh,   g_gh);

    cudaFuncSetAttribute(gemm_bf16_vocab,
                         cudaFuncAttributeMaxDynamicSharedMemorySize, VOC_SMEM);

    static cudaStream_t s_side = nullptr;
    static cudaEvent_t ev_init = nullptr, ev_gh = nullptr;
    if (!s_side) {
        cudaStreamCreateWithFlags(&s_side, cudaStreamNonBlocking);
        cudaEventCreateWithFlags(&ev_init, cudaEventDisableTiming);
        cudaEventCreateWithFlags(&ev_gh,   cudaEventDisableTiming);
    }

    // main: init biases
    init_bias_kernel<<<B_ * 3 * H_ / 256, 256>>>(gh, b_hh, gx, b_ih, x, comb_b);
    cudaEventRecord(ev_init, 0);

    // side branch: gh += hidden @ w_hh^T
    cudaStreamWaitEvent(s_side, ev_init, 0);
    gemm_tf32_splitk<<<dim3(48, 4, 8), 128, 0, s_side>>>(hidden, w_hh, gh, H_, 128, 3 * H_, 0);
    cudaEventRecord(ev_gh, s_side);

    // main chain: attn -> comb -> gx
    attn_kernel<<<B_, 512>>>(ids, hidden, enc, emb, attn_w, attn_b, out_attn, xcat);
    gemm_tf32_splitk<<<dim3(16, 4, 16), 128>>>(xcat, comb_w, x, 2 * H_, 128, H_, 0);
    gemm_tf32_splitk<<<dim3(48, 4, 8), 128>>>(x, w_ih, gx, H_, 128, 3 * H_, 1);

    // join
    cudaStreamWaitEvent(0, ev_gh, 0);
    gru_gate_kernel<<<B_ * H_ / 256, 256>>>(gx, gh, hidden, out_h);

    gemm_bf16_vocab<<<V_ / 128, 512, VOC_SMEM>>>(out_h, out_w, out_logp);
    logsoftmax_kernel<<<B_, 1024>>>(out_logp, out_b);
}